// round 6
// baseline (speedup 1.0000x reference)
#include <cuda_runtime.h>
#include <cuda_bf16.h>

// Problem constants
#define BB   4
#define SS   2048
#define DDIM 1024
#define HH   16
#define HDIM 64
#define SM_SCALE 0.125f   // 64^-0.5

// Intermediates (device globals: allocation-free scratch)
__device__ float g_q[BB * SS * DDIM];
__device__ float g_k[BB * SS * DDIM];
__device__ float g_v[BB * SS * DDIM];
__device__ float g_attn[BB * SS * DDIM];

// Pointer-triple argument for the fused QKV launch (passed by value)
struct GemmTriple {
    const float* A[3];
    const float* W[3];
    float*       C[3];
};

// ---------------------------------------------------------------------------
// GEMM core: C[M,N] = A[M,K] @ Bw[N,K]^T   (row-major, K contiguous: NT gemm)
// 128x128 block tile, BK=16, 256 threads, 8x8 microtile per thread.
// Double-buffered shared memory: global loads for tile t+1 are issued into
// registers while tile t is being consumed; stored to the alternate smem
// buffer right before the single per-iteration __syncthreads.
// ---------------------------------------------------------------------------
__device__ __forceinline__ void gemm_nt_body(
    const float* __restrict__ A, const float* __restrict__ Bw,
    float* __restrict__ C, int M, int N, int K)
{
    __shared__ float As[2][16][132];   // [buf][k][m], padded
    __shared__ float Bs[2][16][132];   // [buf][k][n], padded

    const int tid  = threadIdx.x;
    const int ty   = tid >> 4;      // 0..15
    const int tx   = tid & 15;      // 0..15
    const int brow = blockIdx.y * 128;
    const int bcol = blockIdx.x * 128;

    // Per-thread load coordinates (2 float4 per matrix per tile)
    const int r0  = (tid + 0)   >> 2;        // 0..63
    const int r1  = (tid + 256) >> 2;        // 64..127
    const int c40 = (tid & 3) << 2;          // 0,4,8,12

    float acc[8][8];
#pragma unroll
    for (int i = 0; i < 8; i++)
#pragma unroll
        for (int j = 0; j < 8; j++) acc[i][j] = 0.f;

    // Prologue: load tile 0 into buffer 0
    {
        float4 va0 = *(const float4*)(A  + (size_t)(brow + r0) * K + c40);
        float4 va1 = *(const float4*)(A  + (size_t)(brow + r1) * K + c40);
        float4 vb0 = *(const float4*)(Bw + (size_t)(bcol + r0) * K + c40);
        float4 vb1 = *(const float4*)(Bw + (size_t)(bcol + r1) * K + c40);
        As[0][c40 + 0][r0] = va0.x; As[0][c40 + 1][r0] = va0.y;
        As[0][c40 + 2][r0] = va0.z; As[0][c40 + 3][r0] = va0.w;
        As[0][c40 + 0][r1] = va1.x; As[0][c40 + 1][r1] = va1.y;
        As[0][c40 + 2][r1] = va1.z; As[0][c40 + 3][r1] = va1.w;
        Bs[0][c40 + 0][r0] = vb0.x; Bs[0][c40 + 1][r0] = vb0.y;
        Bs[0][c40 + 2][r0] = vb0.z; Bs[0][c40 + 3][r0] = vb0.w;
        Bs[0][c40 + 0][r1] = vb1.x; Bs[0][c40 + 1][r1] = vb1.y;
        Bs[0][c40 + 2][r1] = vb1.z; Bs[0][c40 + 3][r1] = vb1.w;
    }
    __syncthreads();

    int buf = 0;
    for (int k0 = 0; k0 < K; k0 += 16) {
        const bool has_next = (k0 + 16) < K;
        float4 va0, va1, vb0, vb1;
        if (has_next) {
            const int kn = k0 + 16;
            va0 = *(const float4*)(A  + (size_t)(brow + r0) * K + kn + c40);
            va1 = *(const float4*)(A  + (size_t)(brow + r1) * K + kn + c40);
            vb0 = *(const float4*)(Bw + (size_t)(bcol + r0) * K + kn + c40);
            vb1 = *(const float4*)(Bw + (size_t)(bcol + r1) * K + kn + c40);
        }

#pragma unroll
        for (int k = 0; k < 16; k++) {
            float4 a0 = *(const float4*)&As[buf][k][ty * 8];
            float4 a1 = *(const float4*)&As[buf][k][ty * 8 + 4];
            float4 b0 = *(const float4*)&Bs[buf][k][tx * 8];
            float4 b1 = *(const float4*)&Bs[buf][k][tx * 8 + 4];
            float a[8] = {a0.x, a0.y, a0.z, a0.w, a1.x, a1.y, a1.z, a1.w};
            float b[8] = {b0.x, b0.y, b0.z, b0.w, b1.x, b1.y, b1.z, b1.w};
#pragma unroll
            for (int i = 0; i < 8; i++)
#pragma unroll
                for (int j = 0; j < 8; j++)
                    acc[i][j] = fmaf(a[i], b[j], acc[i][j]);
        }

        if (has_next) {
            const int nb = buf ^ 1;
            As[nb][c40 + 0][r0] = va0.x; As[nb][c40 + 1][r0] = va0.y;
            As[nb][c40 + 2][r0] = va0.z; As[nb][c40 + 3][r0] = va0.w;
            As[nb][c40 + 0][r1] = va1.x; As[nb][c40 + 1][r1] = va1.y;
            As[nb][c40 + 2][r1] = va1.z; As[nb][c40 + 3][r1] = va1.w;
            Bs[nb][c40 + 0][r0] = vb0.x; Bs[nb][c40 + 1][r0] = vb0.y;
            Bs[nb][c40 + 2][r0] = vb0.z; Bs[nb][c40 + 3][r0] = vb0.w;
            Bs[nb][c40 + 0][r1] = vb1.x; Bs[nb][c40 + 1][r1] = vb1.y;
            Bs[nb][c40 + 2][r1] = vb1.z; Bs[nb][c40 + 3][r1] = vb1.w;
            __syncthreads();
            buf = nb;
        }
    }

#pragma unroll
    for (int i = 0; i < 8; i++) {
        float4* cp = (float4*)(C + (size_t)(brow + ty * 8 + i) * N + bcol + tx * 8);
        cp[0] = make_float4(acc[i][0], acc[i][1], acc[i][2], acc[i][3]);
        cp[1] = make_float4(acc[i][4], acc[i][5], acc[i][6], acc[i][7]);
    }
}

// Single GEMM (used for the Wo projection)
__global__ void __launch_bounds__(256) gemm_nt_kernel(
    const float* __restrict__ A, const float* __restrict__ Bw,
    float* __restrict__ C, int M, int N, int K)
{
    gemm_nt_body(A, Bw, C, M, N, K);
}

// Fused QKV: blockIdx.z in {0,1,2} selects (input, weight, output).
// Numerically identical to three separate launches; one CTA pool means one
// ragged scheduling tail instead of three.
__global__ void __launch_bounds__(256) gemm_nt_qkv_kernel(
    GemmTriple t, int M, int N, int K)
{
    const int z = blockIdx.z;
    gemm_nt_body(t.A[z], t.W[z], t.C[z], M, N, K);
}

// ---------------------------------------------------------------------------
// Causal flash attention, fp32.
// Grid: (S/64, H, B). 256 threads (16x16 thread grid).
// Q tile 64 rows, KV tile 32 rows. Online softmax; row <-> half-warp mapping.
// Thread owns rows {ty+16j} (j<4) and cols {tx+16i}.
// Equivalent to ref: exp(-1e9) underflows to 0 => mask+renorm is a no-op.
// ---------------------------------------------------------------------------
#define BQ  64
#define BKV 32

__global__ void __launch_bounds__(256) attn_kernel(
    const float* __restrict__ Q, const float* __restrict__ K,
    const float* __restrict__ V, float* __restrict__ O)
{
    __shared__ float Qs[BQ][HDIM + 4];     // 64 x 68
    __shared__ float Ks[BKV][HDIM + 4];    // 32 x 68
    __shared__ float Vs[BKV][HDIM + 4];    // 32 x 68
    __shared__ float Ps[BQ][BKV + 2];      // 64 x 34

    const int tid = threadIdx.x;
    const int ty  = tid >> 4;   // 0..15
    const int tx  = tid & 15;   // 0..15
    const int qi0 = blockIdx.x * BQ;
    const int h   = blockIdx.y;
    const int b   = blockIdx.z;

    const float* Qb = Q + (size_t)b * SS * DDIM + h * HDIM;
    const float* Kb = K + (size_t)b * SS * DDIM + h * HDIM;
    const float* Vb = V + (size_t)b * SS * DDIM + h * HDIM;

    // Load Q tile (pre-scaled): 64 rows x 16 float4 = 1024 f4, 4 per thread
#pragma unroll
    for (int l = 0; l < 4; l++) {
        int f4 = tid + l * 256;
        int r  = f4 >> 4;
        int c4 = (f4 & 15) << 2;
        float4 v = *(const float4*)(Qb + (size_t)(qi0 + r) * DDIM + c4);
        v.x *= SM_SCALE; v.y *= SM_SCALE; v.z *= SM_SCALE; v.w *= SM_SCALE;
        *(float4*)&Qs[r][c4] = v;
    }

    float o[4][4];
#pragma unroll
    for (int j = 0; j < 4; j++)
#pragma unroll
        for (int i = 0; i < 4; i++) o[j][i] = 0.f;
    float m[4] = {-1e30f, -1e30f, -1e30f, -1e30f};
    float l[4] = {0.f, 0.f, 0.f, 0.f};

    const int nt = (qi0 + BQ) / BKV;
    for (int t = 0; t < nt; t++) {
        const int kj0 = t * BKV;
        __syncthreads();   // prev iteration's reads of Ks/Vs/Ps complete

        // Load K,V tiles: 32 rows x 16 float4 = 512 f4, 2 per thread each
#pragma unroll
        for (int l2 = 0; l2 < 2; l2++) {
            int f4 = tid + l2 * 256;
            int r  = f4 >> 4;
            int c4 = (f4 & 15) << 2;
            *(float4*)&Ks[r][c4] = *(const float4*)(Kb + (size_t)(kj0 + r) * DDIM + c4);
            *(float4*)&Vs[r][c4] = *(const float4*)(Vb + (size_t)(kj0 + r) * DDIM + c4);
        }
        __syncthreads();

        // S = (Q*scale) K^T : 4x2 microtile per thread
        float sv[4][2];
#pragma unroll
        for (int j = 0; j < 4; j++) { sv[j][0] = 0.f; sv[j][1] = 0.f; }
#pragma unroll
        for (int d = 0; d < HDIM; d += 4) {
            float4 qv[4], kv[2];
#pragma unroll
            for (int j = 0; j < 4; j++) qv[j] = *(const float4*)&Qs[ty + 16 * j][d];
#pragma unroll
            for (int i = 0; i < 2; i++) kv[i] = *(const float4*)&Ks[tx + 16 * i][d];
#pragma unroll
            for (int j = 0; j < 4; j++)
#pragma unroll
                for (int i = 0; i < 2; i++)
                    sv[j][i] += qv[j].x * kv[i].x + qv[j].y * kv[i].y
                              + qv[j].z * kv[i].z + qv[j].w * kv[i].w;
        }

        // Causal mask (only tiles touching the diagonal)
        if (kj0 + BKV - 1 > qi0) {
#pragma unroll
            for (int j = 0; j < 4; j++)
#pragma unroll
                for (int i = 0; i < 2; i++)
                    if (kj0 + tx + 16 * i > qi0 + ty + 16 * j) sv[j][i] = -1e30f;
        }

        // Online softmax update (row = half-warp of 16 lanes)
#pragma unroll
        for (int j = 0; j < 4; j++) {
            float rm = fmaxf(sv[j][0], sv[j][1]);
            rm = fmaxf(rm, __shfl_xor_sync(0xffffffffu, rm, 8));
            rm = fmaxf(rm, __shfl_xor_sync(0xffffffffu, rm, 4));
            rm = fmaxf(rm, __shfl_xor_sync(0xffffffffu, rm, 2));
            rm = fmaxf(rm, __shfl_xor_sync(0xffffffffu, rm, 1));
            float mn    = fmaxf(m[j], rm);
            float alpha = __expf(m[j] - mn);
            m[j] = mn;
            float p0 = __expf(sv[j][0] - mn);
            float p1 = __expf(sv[j][1] - mn);
            l[j] = l[j] * alpha + p0 + p1;
#pragma unroll
            for (int i = 0; i < 4; i++) o[j][i] *= alpha;
            Ps[ty + 16 * j][tx]      = p0;
            Ps[ty + 16 * j][tx + 16] = p1;
        }
        __syncthreads();

        // O += P @ V
#pragma unroll 4
        for (int c = 0; c < BKV; c++) {
            float vv[4];
#pragma unroll
            for (int i = 0; i < 4; i++) vv[i] = Vs[c][tx + 16 * i];
#pragma unroll
            for (int j = 0; j < 4; j++) {
                float pv = Ps[ty + 16 * j][c];
#pragma unroll
                for (int i = 0; i < 4; i++) o[j][i] = fmaf(pv, vv[i], o[j][i]);
            }
        }
    }

    // Finalize: reduce l across the row's 16 lanes, divide, write out
    float* Ob = O + (size_t)b * SS * DDIM + h * HDIM;
#pragma unroll
    for (int j = 0; j < 4; j++) {
        float lt = l[j];
        lt += __shfl_xor_sync(0xffffffffu, lt, 8);
        lt += __shfl_xor_sync(0xffffffffu, lt, 4);
        lt += __shfl_xor_sync(0xffffffffu, lt, 2);
        lt += __shfl_xor_sync(0xffffffffu, lt, 1);
        float inv = 1.f / fmaxf(lt, 1e-9f);
        int r = qi0 + ty + 16 * j;
#pragma unroll
        for (int i = 0; i < 4; i++)
            Ob[(size_t)r * DDIM + tx + 16 * i] = o[j][i] * inv;
    }
}

// ---------------------------------------------------------------------------
// Launch
// Inputs (metadata order): 0=query 1=key 2=value 3=attn_mask(unused)
//                          4=Wq 5=Wk 6=Wv 7=Wo. Output: float32 [B,S,DIM].
// ---------------------------------------------------------------------------
extern "C" void kernel_launch(void* const* d_in, const int* in_sizes, int n_in,
                              void* d_out, int out_size)
{
    const float* query = (const float*)d_in[0];
    const float* key   = (const float*)d_in[1];
    const float* value = (const float*)d_in[2];
    const float* Wq    = (const float*)d_in[4];
    const float* Wk    = (const float*)d_in[5];
    const float* Wv    = (const float*)d_in[6];
    const float* Wo    = (const float*)d_in[7];
    float* out = (float*)d_out;

    float *q, *k, *v, *a;
    cudaGetSymbolAddress((void**)&q, g_q);
    cudaGetSymbolAddress((void**)&k, g_k);
    cudaGetSymbolAddress((void**)&v, g_v);
    cudaGetSymbolAddress((void**)&a, g_attn);

    const int M = BB * SS;           // 8192

    GemmTriple t;
    t.A[0] = query; t.A[1] = key; t.A[2] = value;
    t.W[0] = Wq;    t.W[1] = Wk;  t.W[2] = Wv;
    t.C[0] = q;     t.C[1] = k;   t.C[2] = v;

    dim3 gqkv(DDIM / 128, M / 128, 3);   // (8, 64, 3) — one pool, one tail
    gemm_nt_qkv_kernel<<<gqkv, 256>>>(t, M, DDIM, DDIM);

    dim3 ga(SS / BQ, HH, BB);            // (32, 16, 4)
    attn_kernel<<<ga, 256>>>(q, k, v, a);

    dim3 gg(DDIM / 128, M / 128);        // (8, 64)
    gemm_nt_kernel<<<gg, 256>>>(a, Wo, out, M, DDIM, DDIM);
}

// round 16
// speedup vs baseline: 1.3829x; 1.3829x over previous
#include <cuda_runtime.h>
#include <cuda_bf16.h>
#include <cstdint>

// Problem constants
#define BB   4
#define SS   2048
#define DDIM 1024
#define HH   16
#define HDIM 64
#define SM_SCALE 0.125f   // 64^-0.5

// Intermediates (device globals: allocation-free scratch)
__device__ float g_q[BB * SS * DDIM];
__device__ float g_k[BB * SS * DDIM];
__device__ float g_v[BB * SS * DDIM];
__device__ float g_attn[BB * SS * DDIM];

// Pointer-triple argument for the fused QKV launch (passed by value)
struct GemmTriple {
    const float* A[3];
    const float* W[3];
    float*       C[3];
};

// ---------------------------------------------------------------------------
// bf16 split helpers: x = hi + lo, each bf16 (rn). Combined ~17 mantissa bits.
// ---------------------------------------------------------------------------
__device__ __forceinline__ void split_pair(float x, float y,
                                           uint32_t& hi, uint32_t& lo)
{
    __nv_bfloat16 hx = __float2bfloat16_rn(x);
    __nv_bfloat16 hy = __float2bfloat16_rn(y);
    __nv_bfloat16 lx = __float2bfloat16_rn(x - __bfloat162float(hx));
    __nv_bfloat16 ly = __float2bfloat16_rn(y - __bfloat162float(hy));
    __nv_bfloat162 H; H.x = hx; H.y = hy;
    __nv_bfloat162 L; L.x = lx; L.y = ly;
    hi = *reinterpret_cast<uint32_t*>(&H);
    lo = *reinterpret_cast<uint32_t*>(&L);
}

// mma.sync m16n8k16 row.col bf16 -> f32 accumulate
__device__ __forceinline__ void mma_bf16(float& c0, float& c1, float& c2, float& c3,
                                         uint32_t a0, uint32_t a1, uint32_t a2, uint32_t a3,
                                         uint32_t b0, uint32_t b1)
{
    asm volatile(
        "mma.sync.aligned.m16n8k16.row.col.f32.bf16.bf16.f32 "
        "{%0,%1,%2,%3}, {%4,%5,%6,%7}, {%8,%9}, {%0,%1,%2,%3};\n"
        : "+f"(c0), "+f"(c1), "+f"(c2), "+f"(c3)
        : "r"(a0), "r"(a1), "r"(a2), "r"(a3), "r"(b0), "r"(b1));
}

// ---------------------------------------------------------------------------
// Tensor-core GEMM: C[M,N] = A[M,K] @ W[N,K]^T (row-major, K contiguous).
// bf16 hi/lo split, 3 mma passes: Ah*Wh + Ah*Wl + Al*Wh  (Al*Wl ~2^-18, dropped).
// CTA: 128x128 tile, 256 threads = 8 warps (warp tile 64x32), BK=16.
// fp32 loaded from global, split to bf16 in registers, staged to smem
// (double-buffered). Fragments loaded with plain b32 LDS (layout-explicit).
// ---------------------------------------------------------------------------
#define PAD 20   // row stride in bf16 elements (40B = 10 banks)

__device__ __forceinline__ void gemm_nt_body(
    const float* __restrict__ A, const float* __restrict__ Bw,
    float* __restrict__ C, int M, int N, int K)
{
    __shared__ __align__(16) __nv_bfloat16 sAh[2][128][PAD];
    __shared__ __align__(16) __nv_bfloat16 sAl[2][128][PAD];
    __shared__ __align__(16) __nv_bfloat16 sWh[2][128][PAD];
    __shared__ __align__(16) __nv_bfloat16 sWl[2][128][PAD];

    const int tid  = threadIdx.x;
    const int lane = tid & 31;
    const int warp = tid >> 5;          // 0..7
    const int wm   = warp & 1;          // m-tile: 64 rows
    const int wn   = warp >> 1;         // n-tile: 32 cols
    const int g    = lane >> 2;         // 0..7
    const int tig  = lane & 3;          // 0..3

    const int brow = blockIdx.y * 128;
    const int bcol = blockIdx.x * 128;

    // Global load coords: 512 float4 per matrix per stage, 2 per thread.
    const int r0  = tid >> 2;           // 0..63
    const int r1  = r0 + 64;            // 64..127
    const int c40 = (tid & 3) << 2;     // 0,4,8,12

    float acc[4][4][4];
#pragma unroll
    for (int mi = 0; mi < 4; mi++)
#pragma unroll
        for (int ni = 0; ni < 4; ni++)
#pragma unroll
            for (int e = 0; e < 4; e++) acc[mi][ni][e] = 0.f;

    // Convert + store one float4 into hi/lo tiles at [r][c4..c4+3]
    auto store4 = [&](int buf, __nv_bfloat16 (*Th)[128][PAD],
                      __nv_bfloat16 (*Tl)[128][PAD], int r, float4 v) {
        uint32_t h01, l01, h23, l23;
        split_pair(v.x, v.y, h01, l01);
        split_pair(v.z, v.w, h23, l23);
        *reinterpret_cast<uint32_t*>(&Th[buf][r][c40])     = h01;
        *reinterpret_cast<uint32_t*>(&Th[buf][r][c40 + 2]) = h23;
        *reinterpret_cast<uint32_t*>(&Tl[buf][r][c40])     = l01;
        *reinterpret_cast<uint32_t*>(&Tl[buf][r][c40 + 2]) = l23;
    };

    // Prologue: stage 0
    {
        float4 va0 = *(const float4*)(A  + (size_t)(brow + r0) * K + c40);
        float4 va1 = *(const float4*)(A  + (size_t)(brow + r1) * K + c40);
        float4 vw0 = *(const float4*)(Bw + (size_t)(bcol + r0) * K + c40);
        float4 vw1 = *(const float4*)(Bw + (size_t)(bcol + r1) * K + c40);
        store4(0, sAh, sAl, r0, va0);
        store4(0, sAh, sAl, r1, va1);
        store4(0, sWh, sWl, r0, vw0);
        store4(0, sWh, sWl, r1, vw1);
    }
    __syncthreads();

    int buf = 0;
    for (int k0 = 0; k0 < K; k0 += 16) {
        const bool has_next = (k0 + 16) < K;
        float4 va0, va1, vw0, vw1;
        if (has_next) {
            const int kn = k0 + 16;
            va0 = *(const float4*)(A  + (size_t)(brow + r0) * K + kn + c40);
            va1 = *(const float4*)(A  + (size_t)(brow + r1) * K + kn + c40);
            vw0 = *(const float4*)(Bw + (size_t)(bcol + r0) * K + kn + c40);
            vw1 = *(const float4*)(Bw + (size_t)(bcol + r1) * K + kn + c40);
        }

        // ---- compute on current buffer: one k16 step ----
        // Preload all B fragments for this warp's 4 n-subtiles.
        uint32_t wh[4][2], wl[4][2];
#pragma unroll
        for (int ni = 0; ni < 4; ni++) {
            const int rb = wn * 32 + ni * 8 + g;
            wh[ni][0] = *reinterpret_cast<const uint32_t*>(&sWh[buf][rb][2 * tig]);
            wh[ni][1] = *reinterpret_cast<const uint32_t*>(&sWh[buf][rb][2 * tig + 8]);
            wl[ni][0] = *reinterpret_cast<const uint32_t*>(&sWl[buf][rb][2 * tig]);
            wl[ni][1] = *reinterpret_cast<const uint32_t*>(&sWl[buf][rb][2 * tig + 8]);
        }
#pragma unroll
        for (int mi = 0; mi < 4; mi++) {
            const int ra = wm * 64 + mi * 16 + g;
            uint32_t ah0 = *reinterpret_cast<const uint32_t*>(&sAh[buf][ra][2 * tig]);
            uint32_t ah1 = *reinterpret_cast<const uint32_t*>(&sAh[buf][ra + 8][2 * tig]);
            uint32_t ah2 = *reinterpret_cast<const uint32_t*>(&sAh[buf][ra][2 * tig + 8]);
            uint32_t ah3 = *reinterpret_cast<const uint32_t*>(&sAh[buf][ra + 8][2 * tig + 8]);
            uint32_t al0 = *reinterpret_cast<const uint32_t*>(&sAl[buf][ra][2 * tig]);
            uint32_t al1 = *reinterpret_cast<const uint32_t*>(&sAl[buf][ra + 8][2 * tig]);
            uint32_t al2 = *reinterpret_cast<const uint32_t*>(&sAl[buf][ra][2 * tig + 8]);
            uint32_t al3 = *reinterpret_cast<const uint32_t*>(&sAl[buf][ra + 8][2 * tig + 8]);
#pragma unroll
            for (int ni = 0; ni < 4; ni++) {
                float* c = acc[mi][ni];
                mma_bf16(c[0], c[1], c[2], c[3], ah0, ah1, ah2, ah3, wh[ni][0], wh[ni][1]);
                mma_bf16(c[0], c[1], c[2], c[3], ah0, ah1, ah2, ah3, wl[ni][0], wl[ni][1]);
                mma_bf16(c[0], c[1], c[2], c[3], al0, al1, al2, al3, wh[ni][0], wh[ni][1]);
            }
        }

        if (has_next) {
            const int nb = buf ^ 1;
            store4(nb, sAh, sAl, r0, va0);
            store4(nb, sAh, sAl, r1, va1);
            store4(nb, sWh, sWl, r0, vw0);
            store4(nb, sWh, sWl, r1, vw1);
            __syncthreads();
            buf = nb;
        }
    }

    // Epilogue: c0=(g,2tig) c1=(g,2tig+1) c2=(g+8,2tig) c3=(g+8,2tig+1)
#pragma unroll
    for (int mi = 0; mi < 4; mi++) {
        const int row = brow + wm * 64 + mi * 16 + g;
#pragma unroll
        for (int ni = 0; ni < 4; ni++) {
            const int col = bcol + wn * 32 + ni * 8 + 2 * tig;
            float2 v0 = make_float2(acc[mi][ni][0], acc[mi][ni][1]);
            float2 v1 = make_float2(acc[mi][ni][2], acc[mi][ni][3]);
            *(float2*)(C + (size_t)row * N + col)       = v0;
            *(float2*)(C + (size_t)(row + 8) * N + col) = v1;
        }
    }
}

// Single GEMM (Wo projection)
__global__ void __launch_bounds__(256) gemm_nt_kernel(
    const float* __restrict__ A, const float* __restrict__ Bw,
    float* __restrict__ C, int M, int N, int K)
{
    gemm_nt_body(A, Bw, C, M, N, K);
}

// Fused QKV: blockIdx.z selects (input, weight, output)
__global__ void __launch_bounds__(256) gemm_nt_qkv_kernel(
    GemmTriple t, int M, int N, int K)
{
    const int z = blockIdx.z;
    gemm_nt_body(t.A[z], t.W[z], t.C[z], M, N, K);
}

// ---------------------------------------------------------------------------
// Causal flash attention, fp32 (unchanged from the 2711us passing version).
// ---------------------------------------------------------------------------
#define BQ  64
#define BKV 32

__global__ void __launch_bounds__(256) attn_kernel(
    const float* __restrict__ Q, const float* __restrict__ K,
    const float* __restrict__ V, float* __restrict__ O)
{
    __shared__ float Qs[BQ][HDIM + 4];     // 64 x 68
    __shared__ float Ks[BKV][HDIM + 4];    // 32 x 68
    __shared__ float Vs[BKV][HDIM + 4];    // 32 x 68
    __shared__ float Ps[BQ][BKV + 2];      // 64 x 34

    const int tid = threadIdx.x;
    const int ty  = tid >> 4;   // 0..15
    const int tx  = tid & 15;   // 0..15
    const int qi0 = blockIdx.x * BQ;
    const int h   = blockIdx.y;
    const int b   = blockIdx.z;

    const float* Qb = Q + (size_t)b * SS * DDIM + h * HDIM;
    const float* Kb = K + (size_t)b * SS * DDIM + h * HDIM;
    const float* Vb = V + (size_t)b * SS * DDIM + h * HDIM;

#pragma unroll
    for (int l = 0; l < 4; l++) {
        int f4 = tid + l * 256;
        int r  = f4 >> 4;
        int c4 = (f4 & 15) << 2;
        float4 v = *(const float4*)(Qb + (size_t)(qi0 + r) * DDIM + c4);
        v.x *= SM_SCALE; v.y *= SM_SCALE; v.z *= SM_SCALE; v.w *= SM_SCALE;
        *(float4*)&Qs[r][c4] = v;
    }

    float o[4][4];
#pragma unroll
    for (int j = 0; j < 4; j++)
#pragma unroll
        for (int i = 0; i < 4; i++) o[j][i] = 0.f;
    float m[4] = {-1e30f, -1e30f, -1e30f, -1e30f};
    float l[4] = {0.f, 0.f, 0.f, 0.f};

    const int nt = (qi0 + BQ) / BKV;
    for (int t = 0; t < nt; t++) {
        const int kj0 = t * BKV;
        __syncthreads();

#pragma unroll
        for (int l2 = 0; l2 < 2; l2++) {
            int f4 = tid + l2 * 256;
            int r  = f4 >> 4;
            int c4 = (f4 & 15) << 2;
            *(float4*)&Ks[r][c4] = *(const float4*)(Kb + (size_t)(kj0 + r) * DDIM + c4);
            *(float4*)&Vs[r][c4] = *(const float4*)(Vb + (size_t)(kj0 + r) * DDIM + c4);
        }
        __syncthreads();

        float sv[4][2];
#pragma unroll
        for (int j = 0; j < 4; j++) { sv[j][0] = 0.f; sv[j][1] = 0.f; }
#pragma unroll
        for (int d = 0; d < HDIM; d += 4) {
            float4 qv[4], kv[2];
#pragma unroll
            for (int j = 0; j < 4; j++) qv[j] = *(const float4*)&Qs[ty + 16 * j][d];
#pragma unroll
            for (int i = 0; i < 2; i++) kv[i] = *(const float4*)&Ks[tx + 16 * i][d];
#pragma unroll
            for (int j = 0; j < 4; j++)
#pragma unroll
                for (int i = 0; i < 2; i++)
                    sv[j][i] += qv[j].x * kv[i].x + qv[j].y * kv[i].y
                              + qv[j].z * kv[i].z + qv[j].w * kv[i].w;
        }

        if (kj0 + BKV - 1 > qi0) {
#pragma unroll
            for (int j = 0; j < 4; j++)
#pragma unroll
                for (int i = 0; i < 2; i++)
                    if (kj0 + tx + 16 * i > qi0 + ty + 16 * j) sv[j][i] = -1e30f;
        }

#pragma unroll
        for (int j = 0; j < 4; j++) {
            float rm = fmaxf(sv[j][0], sv[j][1]);
            rm = fmaxf(rm, __shfl_xor_sync(0xffffffffu, rm, 8));
            rm = fmaxf(rm, __shfl_xor_sync(0xffffffffu, rm, 4));
            rm = fmaxf(rm, __shfl_xor_sync(0xffffffffu, rm, 2));
            rm = fmaxf(rm, __shfl_xor_sync(0xffffffffu, rm, 1));
            float mn    = fmaxf(m[j], rm);
            float alpha = __expf(m[j] - mn);
            m[j] = mn;
            float p0 = __expf(sv[j][0] - mn);
            float p1 = __expf(sv[j][1] - mn);
            l[j] = l[j] * alpha + p0 + p1;
#pragma unroll
            for (int i = 0; i < 4; i++) o[j][i] *= alpha;
            Ps[ty + 16 * j][tx]      = p0;
            Ps[ty + 16 * j][tx + 16] = p1;
        }
        __syncthreads();

#pragma unroll 4
        for (int c = 0; c < BKV; c++) {
            float vv[4];
#pragma unroll
            for (int i = 0; i < 4; i++) vv[i] = Vs[c][tx + 16 * i];
#pragma unroll
            for (int j = 0; j < 4; j++) {
                float pv = Ps[ty + 16 * j][c];
#pragma unroll
                for (int i = 0; i < 4; i++) o[j][i] = fmaf(pv, vv[i], o[j][i]);
            }
        }
    }

    float* Ob = O + (size_t)b * SS * DDIM + h * HDIM;
#pragma unroll
    for (int j = 0; j < 4; j++) {
        float lt = l[j];
        lt += __shfl_xor_sync(0xffffffffu, lt, 8);
        lt += __shfl_xor_sync(0xffffffffu, lt, 4);
        lt += __shfl_xor_sync(0xffffffffu, lt, 2);
        lt += __shfl_xor_sync(0xffffffffu, lt, 1);
        float inv = 1.f / fmaxf(lt, 1e-9f);
        int r = qi0 + ty + 16 * j;
#pragma unroll
        for (int i = 0; i < 4; i++)
            Ob[(size_t)r * DDIM + tx + 16 * i] = o[j][i] * inv;
    }
}

// ---------------------------------------------------------------------------
// Launch
// Inputs: 0=query 1=key 2=value 3=attn_mask(unused) 4=Wq 5=Wk 6=Wv 7=Wo.
// ---------------------------------------------------------------------------
extern "C" void kernel_launch(void* const* d_in, const int* in_sizes, int n_in,
                              void* d_out, int out_size)
{
    const float* query = (const float*)d_in[0];
    const float* key   = (const float*)d_in[1];
    const float* value = (const float*)d_in[2];
    const float* Wq    = (const float*)d_in[4];
    const float* Wk    = (const float*)d_in[5];
    const float* Wv    = (const float*)d_in[6];
    const float* Wo    = (const float*)d_in[7];
    float* out = (float*)d_out;

    float *q, *k, *v, *a;
    cudaGetSymbolAddress((void**)&q, g_q);
    cudaGetSymbolAddress((void**)&k, g_k);
    cudaGetSymbolAddress((void**)&v, g_v);
    cudaGetSymbolAddress((void**)&a, g_attn);

    const int M = BB * SS;           // 8192

    GemmTriple t;
    t.A[0] = query; t.A[1] = key; t.A[2] = value;
    t.W[0] = Wq;    t.W[1] = Wk;  t.W[2] = Wv;
    t.C[0] = q;     t.C[1] = k;   t.C[2] = v;

    dim3 gqkv(DDIM / 128, M / 128, 3);   // (8, 64, 3)
    gemm_nt_qkv_kernel<<<gqkv, 256>>>(t, M, DDIM, DDIM);

    dim3 ga(SS / BQ, HH, BB);            // (32, 16, 4)
    attn_kernel<<<ga, 256>>>(q, k, v, a);

    dim3 gg(DDIM / 128, M / 128);        // (8, 64)
    gemm_nt_kernel<<<gg, 256>>>(a, Wo, out, M, DDIM, DDIM);
}